// round 1
// baseline (speedup 1.0000x reference)
#include <cuda_runtime.h>
#include <math.h>

#define T_STEPS 8192
#define M_DIM   1024
#define N_DIM   2048

#define GBLOCKS        128
#define ROWS_PER_BLOCK 16    // N_DIM / GBLOCKS
#define RNN_THREADS    256

// Scratch for the batched input projection (allocation-free rule: device global).
__device__ float g_pre[(size_t)T_STEPS * N_DIM];

// Grid barrier state. Sense-reversal: after an even number of barrier uses
// (we use exactly T_STEPS = 8192), both words return to their initial values,
// so the kernel is graph-replay deterministic.
__device__ unsigned g_count = 0;
__device__ volatile unsigned g_sense = 0;

// ---------------------------------------------------------------------------
// Kernel 1: pre = X @ W_ih^T + (b_ih + b_hh)
// X: [T, M] row-major; W_ih: [N, M] row-major (so both are K-major: A*B^T).
// 128x128 block tile, BK=8, 256 threads, 8x8 micro-tile split as 4+4 to keep
// shared loads conflict-free (consecutive lanes read consecutive float4).
// ---------------------------------------------------------------------------
__global__ __launch_bounds__(256) void gemm_pre_kernel(
    const float* __restrict__ X,
    const float* __restrict__ Wih,
    const float* __restrict__ b_ih,
    const float* __restrict__ b_hh)
{
    __shared__ float As[8][128];   // [k][m]
    __shared__ float Bs[8][128];   // [k][n]

    const int tid = threadIdx.x;
    const int rowBase = blockIdx.x * 128;   // along T
    const int colBase = blockIdx.y * 128;   // along N
    const int tx = tid & 15;
    const int ty = tid >> 4;

    float acc[8][8];
#pragma unroll
    for (int i = 0; i < 8; i++)
#pragma unroll
        for (int j = 0; j < 8; j++) acc[i][j] = 0.0f;

    // Loader mapping: each thread loads one float4 of A and one of B per tile.
    const int lr = tid >> 1;          // 0..127 (row within tile)
    const int lq = (tid & 1) * 4;     // 0 or 4 (k offset)

    for (int k0 = 0; k0 < M_DIM; k0 += 8) {
        float4 av = *(const float4*)&X  [(size_t)(rowBase + lr) * M_DIM + k0 + lq];
        float4 bv = *(const float4*)&Wih[(size_t)(colBase + lr) * M_DIM + k0 + lq];

        __syncthreads();   // protect previous tile's consumers
        As[lq + 0][lr] = av.x;
        As[lq + 1][lr] = av.y;
        As[lq + 2][lr] = av.z;
        As[lq + 3][lr] = av.w;
        Bs[lq + 0][lr] = bv.x;
        Bs[lq + 1][lr] = bv.y;
        Bs[lq + 2][lr] = bv.z;
        Bs[lq + 3][lr] = bv.w;
        __syncthreads();

#pragma unroll
        for (int k = 0; k < 8; k++) {
            float4 a0 = ((const float4*)As[k])[ty];
            float4 a1 = ((const float4*)As[k])[ty + 16];
            float4 b0 = ((const float4*)Bs[k])[tx];
            float4 b1 = ((const float4*)Bs[k])[tx + 16];
            float a[8] = {a0.x, a0.y, a0.z, a0.w, a1.x, a1.y, a1.z, a1.w};
            float b[8] = {b0.x, b0.y, b0.z, b0.w, b1.x, b1.y, b1.z, b1.w};
#pragma unroll
            for (int i = 0; i < 8; i++)
#pragma unroll
                for (int j = 0; j < 8; j++)
                    acc[i][j] = fmaf(a[i], b[j], acc[i][j]);
        }
    }

    // Epilogue with fused bias.
    const int n0 = colBase + tx * 4;        // cols j = 0..3
    const int n1 = colBase + 64 + tx * 4;   // cols j = 4..7
    float bias[8];
#pragma unroll
    for (int j = 0; j < 4; j++) {
        bias[j]     = b_ih[n0 + j] + b_hh[n0 + j];
        bias[j + 4] = b_ih[n1 + j] + b_hh[n1 + j];
    }

#pragma unroll
    for (int i = 0; i < 8; i++) {
        int m = rowBase + ((i < 4) ? (ty * 4 + i) : (64 + ty * 4 + (i - 4)));
        float4 o0, o1;
        o0.x = acc[i][0] + bias[0];
        o0.y = acc[i][1] + bias[1];
        o0.z = acc[i][2] + bias[2];
        o0.w = acc[i][3] + bias[3];
        o1.x = acc[i][4] + bias[4];
        o1.y = acc[i][5] + bias[5];
        o1.z = acc[i][6] + bias[6];
        o1.w = acc[i][7] + bias[7];
        *(float4*)&g_pre[(size_t)m * N_DIM + n0] = o0;
        *(float4*)&g_pre[(size_t)m * N_DIM + n1] = o1;
    }
}

// ---------------------------------------------------------------------------
// Grid-wide sense-reversal barrier (all GBLOCKS blocks are co-resident:
// 128 blocks <= 148 SMs at 1 block/SM by shared-memory occupancy).
// ---------------------------------------------------------------------------
__device__ __forceinline__ void gridbar(int step)
{
    __syncthreads();
    if (threadIdx.x == 0) {
        const unsigned want = (unsigned)((step & 1) ^ 1);
        __threadfence();                       // publish this step's writes
        if (atomicAdd(&g_count, 1u) == GBLOCKS - 1) {
            atomicExch(&g_count, 0u);          // reset for next use
            __threadfence();                   // order reset before release
            g_sense = want;                    // release
        } else {
            while (g_sense != want) { }        // acquire (volatile poll in L2)
        }
        __threadfence();                       // make peers' writes visible
    }
    __syncthreads();
}

// ---------------------------------------------------------------------------
// Kernel 2: persistent RNN recurrence.
// Block b owns rows [b*16, b*16+16) of h. W_hh slice lives in SMEM (128 KB).
// Each warp computes 2 rows; h_{t-1} is staged into SMEM from Y[t-1].
// ---------------------------------------------------------------------------
__global__ __launch_bounds__(RNN_THREADS) void rnn_kernel(
    const float* __restrict__ Whh,
    float* __restrict__ Y)
{
    extern __shared__ float smem[];
    float* sW = smem;                                   // 16 * 2048 floats
    float* sh = smem + ROWS_PER_BLOCK * N_DIM;          // 2048 floats

    const int tid  = threadIdx.x;
    const int b    = blockIdx.x;
    const int warp = tid >> 5;
    const int lane = tid & 31;

    // Load this block's W_hh slice into SMEM (once).
    {
        const float4* Wg  = (const float4*)(Whh + (size_t)b * ROWS_PER_BLOCK * N_DIM);
        float4* sW4 = (float4*)sW;
        const int n4 = ROWS_PER_BLOCK * N_DIM / 4;      // 8192
#pragma unroll 4
        for (int i = tid; i < n4; i += RNN_THREADS) sW4[i] = Wg[i];
    }

    // Step 0: h_0 = 0  =>  Y[0] = tanh(pre[0]).
    if (tid < ROWS_PER_BLOCK) {
        int r = b * ROWS_PER_BLOCK + tid;
        Y[r] = tanhf(g_pre[r]);
    }
    gridbar(0);   // also orders the SMEM W load for all threads

    const float4* w0  = (const float4*)(sW + (size_t)(2 * warp)     * N_DIM);
    const float4* w1  = (const float4*)(sW + (size_t)(2 * warp + 1) * N_DIM);
    float4* sh4 = (float4*)sh;
    const int row0 = b * ROWS_PER_BLOCK + 2 * warp;

    for (int t = 1; t < T_STEPS; t++) {
        // Stage h_{t-1} (= Y[t-1]) into SMEM; issue pre loads early so their
        // DRAM latency hides behind the dot products.
        const float4* Yp = (const float4*)(Y + (size_t)(t - 1) * N_DIM);
        float2 p = *(const float2*)(g_pre + (size_t)t * N_DIM + row0);
        sh4[tid]       = Yp[tid];
        sh4[tid + 256] = Yp[tid + 256];
        __syncthreads();

        float acc0 = 0.0f, acc1 = 0.0f;
#pragma unroll
        for (int i = 0; i < 16; i++) {
            int c = i * 32 + lane;
            float4 h4 = sh4[c];
            float4 a  = w0[c];
            float4 bb = w1[c];
            acc0 = fmaf(a.x,  h4.x, acc0);
            acc0 = fmaf(a.y,  h4.y, acc0);
            acc0 = fmaf(a.z,  h4.z, acc0);
            acc0 = fmaf(a.w,  h4.w, acc0);
            acc1 = fmaf(bb.x, h4.x, acc1);
            acc1 = fmaf(bb.y, h4.y, acc1);
            acc1 = fmaf(bb.z, h4.z, acc1);
            acc1 = fmaf(bb.w, h4.w, acc1);
        }
#pragma unroll
        for (int o = 16; o; o >>= 1) {
            acc0 += __shfl_xor_sync(0xffffffffu, acc0, o);
            acc1 += __shfl_xor_sync(0xffffffffu, acc1, o);
        }
        if (lane == 0) {
            float2 out;
            out.x = tanhf(p.x + acc0);
            out.y = tanhf(p.y + acc1);
            *(float2*)(Y + (size_t)t * N_DIM + row0) = out;
        }
        gridbar(t);
    }
}

// ---------------------------------------------------------------------------
extern "C" void kernel_launch(void* const* d_in, const int* in_sizes, int n_in,
                              void* d_out, int out_size)
{
    const float* X   = (const float*)d_in[0];   // [T, M]
    const float* Wih = (const float*)d_in[1];   // [N, M]
    const float* Whh = (const float*)d_in[2];   // [N, N]
    const float* bih = (const float*)d_in[3];   // [N]
    const float* bhh = (const float*)d_in[4];   // [N]
    float* Y = (float*)d_out;                   // [T, N]

    dim3 ggrid(T_STEPS / 128, N_DIM / 128);
    gemm_pre_kernel<<<ggrid, 256>>>(X, Wih, bih, bhh);

    size_t smem_bytes = (size_t)(ROWS_PER_BLOCK * N_DIM + N_DIM) * sizeof(float);
    cudaFuncSetAttribute(rnn_kernel,
                         cudaFuncAttributeMaxDynamicSharedMemorySize,
                         (int)smem_bytes);
    rnn_kernel<<<GBLOCKS, RNN_THREADS, smem_bytes>>>(Whh, Y);
}